// round 12
// baseline (speedup 1.0000x reference)
#include <cuda_runtime.h>
#include <cuda_fp16.h>
#include <cstdint>

// ---------------------------------------------------------------------------
// SwinBlock sm_103a round 11:
//  - GEMM: 256 threads, 8 warps (4m x 2n), warp tile 64x64 (2x FLOP/smem-byte
//    vs round 10), BK=64, 3-stage cp.async load-at-top pipeline.
//  - Attention flash-style, LN, merged wconv: unchanged from round 10.
// ---------------------------------------------------------------------------

#define TOK   65536
#define CEMB  512
#define FFN   2048

__device__ __half g_axA [(size_t)TOK * CEMB];
__device__ __half g_asA [(size_t)TOK * CEMB];
__device__ __half g_kv  [(size_t)TOK * 1024];
__device__ __half g_q   [(size_t)TOK * CEMB];
__device__ float  g_xres[(size_t)TOK * CEMB];
__device__ __half g_hA  [(size_t)TOK * FFN];
__device__ __half g_wqkvB[1024 * 512];
__device__ __half g_wskipB[512 * 512];
__device__ __half g_wprojB[512 * 512];
__device__ __half g_wfc1B[2048 * 512];
__device__ __half g_wfc2B[512 * 2048];

__device__ __forceinline__ int wt_to_nat(int wt) {
    int n   = wt & 63;
    int win = wt >> 6;
    int wi  = win & 63;
    int b   = win >> 6;
    int hp  = ((wi >> 3) << 3) + (n >> 3);
    int wp  = ((wi & 7)  << 3) + (n & 7);
    int h   = (hp + 4) & 63;
    int w   = (wp + 4) & 63;
    return (b << 12) + (h << 6) + w;
}

__device__ __forceinline__ uint32_t pk2(float a, float b) {
    __half2 h = __floats2half2_rn(a, b);
    return *(uint32_t*)&h;
}

__device__ __forceinline__ void mma16(float c[4], const uint32_t a[4],
                                      uint32_t b0, uint32_t b1) {
    asm volatile(
        "mma.sync.aligned.m16n8k16.row.col.f32.f16.f16.f32 "
        "{%0,%1,%2,%3}, {%4,%5,%6,%7}, {%8,%9}, {%0,%1,%2,%3};\n"
        : "+f"(c[0]), "+f"(c[1]), "+f"(c[2]), "+f"(c[3])
        : "r"(a[0]), "r"(a[1]), "r"(a[2]), "r"(a[3]), "r"(b0), "r"(b1));
}

__device__ __forceinline__ void cpa16(uint32_t dst, const void* src) {
    asm volatile("cp.async.cg.shared.global [%0], [%1], 16;\n" :: "r"(dst), "l"(src));
}
__device__ __forceinline__ void cpa_commit() { asm volatile("cp.async.commit_group;\n"); }
__device__ __forceinline__ void cpa_wait1()  { asm volatile("cp.async.wait_group 1;\n"); }
__device__ __forceinline__ void cpa_wait0()  { asm volatile("cp.async.wait_group 0;\n"); }

// ---------------------------------------------------------------------------
// LayerNorm -> f32 smem staging -> fp16 A-layout write. (unchanged)
// ---------------------------------------------------------------------------
__device__ __forceinline__ void ln_row_st(const float* __restrict__ in,
                                          const float* __restrict__ g,
                                          const float* __restrict__ b,
                                          float* __restrict__ stgrow, int lane) {
    float4 v[4];
    float s = 0.f, sq = 0.f;
#pragma unroll
    for (int j = 0; j < 4; j++) {
        v[j] = *(const float4*)(in + (((j << 5) + lane) << 2));
        s  += v[j].x + v[j].y + v[j].z + v[j].w;
        sq += v[j].x*v[j].x + v[j].y*v[j].y + v[j].z*v[j].z + v[j].w*v[j].w;
    }
#pragma unroll
    for (int o = 16; o; o >>= 1) {
        s  += __shfl_xor_sync(0xffffffffu, s, o);
        sq += __shfl_xor_sync(0xffffffffu, sq, o);
    }
    float mean = s * (1.f / 512.f);
    float var  = sq * (1.f / 512.f) - mean * mean;
    float rstd = rsqrtf(var + 1e-5f);
#pragma unroll
    for (int j = 0; j < 4; j++) {
        int off = (((j << 5) + lane) << 2);
        float4 gg = *(const float4*)(g + off);
        float4 bb = *(const float4*)(b + off);
        stgrow[off + 0] = (v[j].x - mean) * rstd * gg.x + bb.x;
        stgrow[off + 1] = (v[j].y - mean) * rstd * gg.y + bb.y;
        stgrow[off + 2] = (v[j].z - mean) * rstd * gg.z + bb.z;
        stgrow[off + 3] = (v[j].w - mean) * rstd * gg.w + bb.w;
    }
}

__device__ __forceinline__ void stg_writeA16(__half* __restrict__ out, int row0,
                                             const float (*stg)[516]) {
    size_t base = (size_t)(row0 >> 7) * (128 * 512) + (size_t)((row0 >> 4) & 7) * 256;
#pragma unroll
    for (int i = 0; i < 2; i++) {
        int f4  = threadIdx.x + (i << 9);
        int kb16 = f4 >> 5;
        int lane = f4 & 31;
        int lr = lane >> 2, tq = lane & 3;
        int c0 = (kb16 << 4) + (tq << 1);
        uint4 o;
        o.x = pk2(stg[lr    ][c0    ], stg[lr    ][c0 + 1]);
        o.y = pk2(stg[lr + 8][c0    ], stg[lr + 8][c0 + 1]);
        o.z = pk2(stg[lr    ][c0 + 8], stg[lr    ][c0 + 9]);
        o.w = pk2(stg[lr + 8][c0 + 8], stg[lr + 8][c0 + 9]);
        *(uint4*)(out + base + (size_t)kb16 * 2048 + lane * 8) = o;
    }
}

__global__ __launch_bounds__(512) void ln1_kernel(const float* __restrict__ x,
                                                  const float* __restrict__ skip,
                                                  const float* __restrict__ g1,
                                                  const float* __restrict__ b1,
                                                  __half* __restrict__ outxA,
                                                  __half* __restrict__ outsA) {
    __shared__ float stg[16][516];
    int warp = threadIdx.x >> 5, lane = threadIdx.x & 31;
    int row0 = blockIdx.x << 4;
    int nat  = wt_to_nat(row0 + warp);
    ln_row_st(x + (size_t)nat * CEMB, g1, b1, stg[warp], lane);
    __syncthreads();
    stg_writeA16(outxA, row0, stg);
    __syncthreads();
    ln_row_st(skip + (size_t)nat * CEMB, g1, b1, stg[warp], lane);
    __syncthreads();
    stg_writeA16(outsA, row0, stg);
}

__global__ __launch_bounds__(512) void ln2_kernel(const float* __restrict__ xin,
                                                  const float* __restrict__ g2,
                                                  const float* __restrict__ b2,
                                                  __half* __restrict__ outA) {
    __shared__ float stg[16][516];
    int warp = threadIdx.x >> 5, lane = threadIdx.x & 31;
    int row0 = blockIdx.x << 4;
    ln_row_st(xin + (size_t)(row0 + warp) * CEMB, g2, b2, stg[warp], lane);
    __syncthreads();
    stg_writeA16(outA, row0, stg);
}

// merged weight converter (unchanged)
__global__ __launch_bounds__(256) void wconv_all(const float* __restrict__ w0,
                                                 const float* __restrict__ w1,
                                                 const float* __restrict__ w2,
                                                 const float* __restrict__ w3,
                                                 const float* __restrict__ w4,
                                                 __half* __restrict__ o0,
                                                 __half* __restrict__ o1,
                                                 __half* __restrict__ o2,
                                                 __half* __restrict__ o3,
                                                 __half* __restrict__ o4) {
    int id = blockIdx.x * 256 + threadIdx.x;
    const float* w; __half* out; int K; int lid;
    if (id < 65536)       { w = w0; out = o0; K = 512;  lid = id; }
    else if (id < 98304)  { w = w1; out = o1; K = 512;  lid = id - 65536; }
    else if (id < 131072) { w = w2; out = o2; K = 512;  lid = id - 98304; }
    else if (id < 262144) { w = w3; out = o3; K = 512;  lid = id - 131072; }
    else                  { w = w4; out = o4; K = 2048; lid = id - 262144; }
    size_t p0 = (size_t)lid << 3;
    int tp   = K << 7;
    int tile = (int)(p0 / tp);
    int rem  = (int)(p0 - (size_t)tile * tp);
    int kb16 = rem >> 11;
    int rem2 = rem & 2047;
    int ngrp = rem2 >> 8;
    int lane = (rem2 & 255) >> 3;
    int g = lane >> 2, tq = lane & 3;
    int n = (tile << 7) + (ngrp << 4) + g;
    int k = (kb16 << 4) + (tq << 1);
    uint4 o;
    o.x = pk2(w[(size_t)n * K + k],       w[(size_t)n * K + k + 1]);
    o.y = pk2(w[(size_t)n * K + k + 8],   w[(size_t)n * K + k + 9]);
    o.z = pk2(w[(size_t)(n + 8) * K + k],     w[(size_t)(n + 8) * K + k + 1]);
    o.w = pk2(w[(size_t)(n + 8) * K + k + 8], w[(size_t)(n + 8) * K + k + 9]);
    *(uint4*)(out + p0) = o;
}

// ---------------------------------------------------------------------------
// GEMM fp16: 256 threads, 8 warps (4m x 2n), warp 64x64, BK=64, 3 stages,
// load-at-top. EPI: 0 +bias->h | 1 *scale->h | 2 +res f32 scatter | 3 gelu->A
// | 4 +res f32
// ---------------------------------------------------------------------------
#define STG_BYTES 49152
#define GEMM_SMEM (3 * STG_BYTES)

template <int EPI>
__global__ __launch_bounds__(256, 1) void gemm_h(const __half* __restrict__ A,
                                                 const __half* __restrict__ W,
                                                 const float* __restrict__ bias,
                                                 float* __restrict__ out,
                                                 const float* __restrict__ res,
                                                 __half* __restrict__ outh,
                                                 int N, int K) {
    extern __shared__ __align__(16) char smem[];
    const uint32_t sb = (uint32_t)__cvta_generic_to_shared(smem);
    const int tid  = threadIdx.x;
    const int warp = tid >> 5, lane = tid & 31;
    const int wm   = warp >> 1;           // 0..3: 64-row band
    const int wn   = warp & 1;            // 0..1: 64-col band
    const int g    = lane >> 2, tq = lane & 3;
    const int bm   = blockIdx.y * 256;
    const int bn   = blockIdx.x * 128;

    const size_t aTile = (size_t)(bm >> 7) * 128 * K;
    const size_t bTile = (size_t)(bn >> 7) * 128 * K;

    float acc[4][8][4];
#pragma unroll
    for (int i = 0; i < 4; i++)
#pragma unroll
        for (int j = 0; j < 8; j++)
#pragma unroll
            for (int l = 0; l < 4; l++) acc[i][j][l] = 0.f;

    auto load_stage = [&](int s, int kb) {
        const uint32_t dst = sb + (uint32_t)s * STG_BYTES;
        const size_t ko = (size_t)kb * 8192;
#pragma unroll
        for (int j = 0; j < 8; j++) {            // A: 2048 x 16B
            int f4 = tid + (j << 8);
            int tile = f4 >> 10;
            int rem  = f4 & 1023;
            cpa16(dst + (uint32_t)f4 * 16,
                  A + aTile + (size_t)tile * 128 * K + ko + ((size_t)rem << 3));
        }
#pragma unroll
        for (int j = 0; j < 4; j++) {            // B: 1024 x 16B
            int f4 = tid + (j << 8);
            cpa16(dst + 32768 + (uint32_t)f4 * 16, W + bTile + ko + ((size_t)f4 << 3));
        }
    };

    const int nkb = K >> 6;
    load_stage(0, 0); cpa_commit();
    load_stage(1, 1); cpa_commit();

    const uint32_t aOffW = ((uint32_t)(wm >> 1)) * 16384 + ((wm & 1) * 4) * 512 + lane * 16;
    const uint32_t bOffW = 32768 + ((uint32_t)wn * 4) * 512 + lane * 16;

    int stage = 0;
    for (int kb = 0; kb < nkb; kb++) {
        cpa_wait1();
        __syncthreads();
        if (kb + 2 < nkb) {
            int ns = stage + 2; if (ns >= 3) ns -= 3;
            load_stage(ns, kb + 2);
        }
        cpa_commit();

        const char* st = smem + (size_t)stage * STG_BYTES;
#pragma unroll
        for (int kl = 0; kl < 4; kl++) {
            uint4 a[4], b[4];
#pragma unroll
            for (int mi = 0; mi < 4; mi++)
                a[mi] = *(const uint4*)(st + aOffW + kl * 4096 + mi * 512);
#pragma unroll
            for (int nj = 0; nj < 4; nj++)
                b[nj] = *(const uint4*)(st + bOffW + kl * 4096 + nj * 512);
#pragma unroll
            for (int mi = 0; mi < 4; mi++) {
                uint32_t ar[4] = {a[mi].x, a[mi].y, a[mi].z, a[mi].w};
#pragma unroll
                for (int nj = 0; nj < 4; nj++) {
                    mma16(acc[mi][2 * nj],     ar, b[nj].x, b[nj].y);
                    mma16(acc[mi][2 * nj + 1], ar, b[nj].z, b[nj].w);
                }
            }
        }
        stage++; if (stage >= 3) stage = 0;
    }

    if (EPI == 3) {
        cpa_wait0();
        __syncthreads();
        float* stg = (float*)smem;   // [128][132]
#pragma unroll
        for (int half = 0; half < 2; half++) {
            if ((wm >> 1) == half) {
                const int lrb = (wm & 1) * 64;
#pragma unroll
                for (int mi = 0; mi < 4; mi++)
#pragma unroll
                    for (int n8 = 0; n8 < 8; n8++) {
                        int lc = wn * 64 + n8 * 8 + (tq << 1);
                        float bv0 = bias[bn + lc], bv1 = bias[bn + lc + 1];
#pragma unroll
                        for (int hr = 0; hr < 2; hr++) {
                            int lr = lrb + mi * 16 + g + hr * 8;
                            float v0 = acc[mi][n8][hr * 2]     + bv0;
                            float v1 = acc[mi][n8][hr * 2 + 1] + bv1;
                            const float is2 = 0.70710678118654752f;
                            stg[lr * 132 + lc]     = 0.5f * v0 * (1.f + erff(v0 * is2));
                            stg[lr * 132 + lc + 1] = 0.5f * v1 * (1.f + erff(v1 * is2));
                        }
                    }
            }
            __syncthreads();
            size_t tbase = (size_t)((bm >> 7) + half) * 128 * N;
#pragma unroll
            for (int i = 0; i < 8; i++) {
                int f4   = tid + (i << 8);
                int kb16L = f4 >> 8;
                int grp  = (f4 >> 5) & 7;
                int ln2  = f4 & 31;
                int lr   = (grp << 4) + (ln2 >> 2);
                int c0   = (kb16L << 4) + ((ln2 & 3) << 1);
                uint4 o;
                o.x = pk2(stg[lr * 132 + c0],           stg[lr * 132 + c0 + 1]);
                o.y = pk2(stg[(lr + 8) * 132 + c0],     stg[(lr + 8) * 132 + c0 + 1]);
                o.z = pk2(stg[lr * 132 + c0 + 8],       stg[lr * 132 + c0 + 9]);
                o.w = pk2(stg[(lr + 8) * 132 + c0 + 8], stg[(lr + 8) * 132 + c0 + 9]);
                *(uint4*)(outh + tbase + (size_t)((bn >> 4) + kb16L) * 2048
                          + (size_t)grp * 256 + ln2 * 8) = o;
            }
            __syncthreads();
        }
        return;
    }

#pragma unroll
    for (int mi = 0; mi < 4; mi++) {
#pragma unroll
        for (int hr = 0; hr < 2; hr++) {
            int r = bm + wm * 64 + mi * 16 + g + hr * 8;
            size_t obase;
            if (EPI == 2) obase = (size_t)wt_to_nat(r) * CEMB;
            else          obase = (size_t)r * N;
#pragma unroll
            for (int n8 = 0; n8 < 8; n8++) {
                int c = bn + wn * 64 + n8 * 8 + (tq << 1);
                float v0 = acc[mi][n8][hr * 2]     + bias[c];
                float v1 = acc[mi][n8][hr * 2 + 1] + bias[c + 1];
                if (EPI == 0) {
                    *(uint32_t*)(outh + obase + c) = pk2(v0, v1);
                } else if (EPI == 1) {
                    const float sc = 0.17677669529663687f;
                    *(uint32_t*)(outh + obase + c) = pk2(v0 * sc, v1 * sc);
                } else {
                    v0 += res[obase + c];
                    v1 += res[obase + c + 1];
                    *(float2*)(out + obase + c) = make_float2(v0, v1);
                }
            }
        }
    }
}

// ---------------------------------------------------------------------------
// Windowed attention, flash-style (unchanged from round 10).
// ---------------------------------------------------------------------------
__global__ __launch_bounds__(256) void attn_kernel(const __half* __restrict__ q,
                                                   const __half* __restrict__ kv,
                                                   const float* __restrict__ rb,
                                                   __half* __restrict__ outA) {
    __shared__ __align__(16) __half sqh[64][40];
    __shared__ __align__(16) __half skh[64][40];
    __shared__ __align__(16) __half svT[32][72];
    __shared__ float redm[2][64];
    __shared__ float reds[2][64];
    __shared__ float soP[2][64][36];

    const int tid  = threadIdx.x;
    const int warp = tid >> 5, lane = tid & 31;
    const int g    = lane >> 2, tq = lane & 3;
    const int wm   = warp >> 1;
    const int wn   = warp & 1;
    const int tn0  = wm << 4;
    const int n00  = wn << 5;
    const int win  = blockIdx.x;
    const int wi   = win & 63;
    const int wr   = wi >> 3, wc = wi & 7;
    const int base = win << 6;
    const int h0   = blockIdx.y << 2;
    const size_t tbase = (size_t)(win >> 1) * (128 * 512);
    const int grpBase = (win & 1) * 4;

    for (int h = h0; h < h0 + 4; h++) {
        {
            int rown = tid >> 2;
            int ch   = tid & 3;
            *(uint4*)&sqh[rown][ch << 3] =
                *(const uint4*)(q  + (size_t)(base + rown) * 512  + h * 32 + (ch << 3));
            *(uint4*)&skh[rown][ch << 3] =
                *(const uint4*)(kv + (size_t)(base + rown) * 1024 + h * 32 + (ch << 3));
            union { uint4 u; __half hs[8]; } vv;
            vv.u = *(const uint4*)(kv + (size_t)(base + rown) * 1024 + 512 + h * 32 + (ch << 3));
#pragma unroll
            for (int dd = 0; dd < 8; dd++)
                svT[(ch << 3) + dd][rown] = vv.hs[dd];
        }
        __syncthreads();

        float s[4][4];
        {
            uint32_t aF[2][4];
#pragma unroll
            for (int ks = 0; ks < 2; ks++) {
                int k0 = ks << 4;
                aF[ks][0] = *(const uint32_t*)&sqh[tn0 + g    ][(tq << 1) + k0];
                aF[ks][1] = *(const uint32_t*)&sqh[tn0 + g + 8][(tq << 1) + k0];
                aF[ks][2] = *(const uint32_t*)&sqh[tn0 + g    ][(tq << 1) + 8 + k0];
                aF[ks][3] = *(const uint32_t*)&sqh[tn0 + g + 8][(tq << 1) + 8 + k0];
            }
#pragma unroll
            for (int nj = 0; nj < 4; nj++) {
#pragma unroll
                for (int l = 0; l < 4; l++) s[nj][l] = 0.f;
#pragma unroll
                for (int ks = 0; ks < 2; ks++) {
                    int k0 = ks << 4;
                    uint32_t b0 = *(const uint32_t*)&skh[n00 + (nj << 3) + g][(tq << 1) + k0];
                    uint32_t b1 = *(const uint32_t*)&skh[n00 + (nj << 3) + g][(tq << 1) + 8 + k0];
                    mma16(s[nj], aF[ks], b0, b1);
                }
            }
#pragma unroll
            for (int hr = 0; hr < 2; hr++) {
                int n = tn0 + g + (hr << 3);
                int cn = 15 * (n >> 3) + (n & 7);
                int rhn = (wr == 7) ? (((n >> 3) < 4) ? 1 : 2) : 0;
                int rwn = (wc == 7) ? (((n & 7)  < 4) ? 1 : 2) : 0;
                int regn = rhn * 3 + rwn;
#pragma unroll
                for (int nj = 0; nj < 4; nj++)
#pragma unroll
                    for (int cc = 0; cc < 2; cc++) {
                        int m = n00 + (nj << 3) + (tq << 1) + cc;
                        int m2 = 63 - m;
                        int cm = 15 * (m2 >> 3) + (m2 & 7);
                        float bv = rb[(cn + cm) * 16 + h];
                        int rhm = (wr == 7) ? (((m >> 3) < 4) ? 1 : 2) : 0;
                        int rwm = (wc == 7) ? (((m & 7)  < 4) ? 1 : 2) : 0;
                        float msk = ((rhm * 3 + rwm) != regn) ? -100.f : 0.f;
                        s[nj][hr * 2 + cc] += bv + msk;
                    }
            }
        }

        float e[4][4], scl0, scl1;
        {
            float mx0 = -1e30f, mx1 = -1e30f;
#pragma unroll
            for (int nj = 0; nj < 4; nj++) {
                mx0 = fmaxf(mx0, fmaxf(s[nj][0], s[nj][1]));
                mx1 = fmaxf(mx1, fmaxf(s[nj][2], s[nj][3]));
            }
            mx0 = fmaxf(mx0, __shfl_xor_sync(0xffffffffu, mx0, 1));
            mx0 = fmaxf(mx0, __shfl_xor_sync(0xffffffffu, mx0, 2));
            mx1 = fmaxf(mx1, __shfl_xor_sync(0xffffffffu, mx1, 1));
            mx1 = fmaxf(mx1, __shfl_xor_sync(0xffffffffu, mx1, 2));
            float sm0 = 0.f, sm1 = 0.f;
#pragma unroll
            for (int nj = 0; nj < 4; nj++) {
                e[nj][0] = expf(s[nj][0] - mx0);
                e[nj][1] = expf(s[nj][1] - mx0);
                e[nj][2] = expf(s[nj][2] - mx1);
                e[nj][3] = expf(s[nj][3] - mx1);
                sm0 += e[nj][0] + e[nj][1];
                sm1 += e[nj][2] + e[nj][3];
            }
            sm0 += __shfl_xor_sync(0xffffffffu, sm0, 1);
            sm0 += __shfl_xor_sync(0xffffffffu, sm0, 2);
            sm1 += __shfl_xor_sync(0xffffffffu, sm1, 1);
            sm1 += __shfl_xor_sync(0xffffffffu, sm1, 2);
            if (tq == 0) {
                redm[wn][tn0 + g]     = mx0;  reds[wn][tn0 + g]     = sm0;
                redm[wn][tn0 + g + 8] = mx1;  reds[wn][tn0 + g + 8] = sm1;
            }
            __syncthreads();
            int r0 = tn0 + g, r1 = tn0 + g + 8;
            float Ma = fmaxf(redm[0][r0], redm[1][r0]);
            float den0 = reds[0][r0] * expf(redm[0][r0] - Ma)
                       + reds[1][r0] * expf(redm[1][r0] - Ma);
            scl0 = expf(mx0 - Ma) / den0;
            float Mb = fmaxf(redm[0][r1], redm[1][r1]);
            float den1 = reds[0][r1] * expf(redm[0][r1] - Mb)
                       + reds[1][r1] * expf(redm[1][r1] - Mb);
            scl1 = expf(mx1 - Mb) / den1;
        }

        uint32_t aP[2][4];
#pragma unroll
        for (int kj = 0; kj < 2; kj++) {
            int njl = kj * 2, njh = kj * 2 + 1;
            aP[kj][0] = pk2(e[njl][0] * scl0, e[njl][1] * scl0);
            aP[kj][1] = pk2(e[njl][2] * scl1, e[njl][3] * scl1);
            aP[kj][2] = pk2(e[njh][0] * scl0, e[njh][1] * scl0);
            aP[kj][3] = pk2(e[njh][2] * scl1, e[njh][3] * scl1);
        }

        float accO[4][4];
#pragma unroll
        for (int dj = 0; dj < 4; dj++)
#pragma unroll
            for (int l = 0; l < 4; l++) accO[dj][l] = 0.f;
#pragma unroll
        for (int kj = 0; kj < 2; kj++) {
            int kbase = n00 + (kj << 4) + (tq << 1);
#pragma unroll
            for (int dj = 0; dj < 4; dj++) {
                uint32_t b0 = *(const uint32_t*)&svT[(dj << 3) + g][kbase];
                uint32_t b1 = *(const uint32_t*)&svT[(dj << 3) + g][kbase + 8];
                mma16(accO[dj], aP[kj], b0, b1);
            }
        }
#pragma unroll
        for (int dj = 0; dj < 4; dj++)
#pragma unroll
            for (int hr = 0; hr < 2; hr++) {
                int rr = tn0 + g + (hr << 3);
                int dd = (dj << 3) + (tq << 1);
                *(float2*)&soP[wn][rr][dd] =
                    make_float2(accO[dj][hr * 2], accO[dj][hr * 2 + 1]);
            }
        __syncthreads();

        {
            int kb16L = tid >> 7;
            int grpL  = (tid >> 5) & 3;
            int ln2   = tid & 31;
            int lr    = (grpL << 4) + (ln2 >> 2);
            int c0    = (kb16L << 4) + ((ln2 & 3) << 1);
            uint4 o;
            o.x = pk2(soP[0][lr][c0]         + soP[1][lr][c0],
                      soP[0][lr][c0 + 1]     + soP[1][lr][c0 + 1]);
            o.y = pk2(soP[0][lr + 8][c0]     + soP[1][lr + 8][c0],
                      soP[0][lr + 8][c0 + 1] + soP[1][lr + 8][c0 + 1]);
            o.z = pk2(soP[0][lr][c0 + 8]     + soP[1][lr][c0 + 8],
                      soP[0][lr][c0 + 9]     + soP[1][lr][c0 + 9]);
            o.w = pk2(soP[0][lr + 8][c0 + 8] + soP[1][lr + 8][c0 + 8],
                      soP[0][lr + 8][c0 + 9] + soP[1][lr + 8][c0 + 9]);
            *(uint4*)(outA + tbase + (size_t)(2 * h + kb16L) * 2048
                      + (size_t)(grpBase + grpL) * 256 + ln2 * 8) = o;
        }
        __syncthreads();
    }
}

// ---------------------------------------------------------------------------
extern "C" void kernel_launch(void* const* d_in, const int* in_sizes, int n_in,
                              void* d_out, int out_size) {
    const float* x      = (const float*)d_in[0];
    const float* skip   = (const float*)d_in[1];
    const float* n1g    = (const float*)d_in[2];
    const float* n1b    = (const float*)d_in[3];
    const float* w_qkv  = (const float*)d_in[4];
    const float* b_qkv  = (const float*)d_in[5];
    const float* w_skip = (const float*)d_in[6];
    const float* b_skip = (const float*)d_in[7];
    const float* relb   = (const float*)d_in[8];
    const float* w_proj = (const float*)d_in[9];
    const float* b_proj = (const float*)d_in[10];
    const float* n2g    = (const float*)d_in[11];
    const float* n2b    = (const float*)d_in[12];
    const float* w_fc1  = (const float*)d_in[13];
    const float* b_fc1  = (const float*)d_in[14];
    const float* w_fc2  = (const float*)d_in[15];
    const float* b_fc2  = (const float*)d_in[16];
    float* outp = (float*)d_out;

    __half *axA, *asA, *hA, *wqB, *wsB, *wpB, *w1B, *w2B, *kvb, *qb;
    float *xres;
    cudaGetSymbolAddress((void**)&axA, g_axA);
    cudaGetSymbolAddress((void**)&asA, g_asA);
    cudaGetSymbolAddress((void**)&kvb, g_kv);
    cudaGetSymbolAddress((void**)&qb,  g_q);
    cudaGetSymbolAddress((void**)&xres, g_xres);
    cudaGetSymbolAddress((void**)&hA,  g_hA);
    cudaGetSymbolAddress((void**)&wqB, g_wqkvB);
    cudaGetSymbolAddress((void**)&wsB, g_wskipB);
    cudaGetSymbolAddress((void**)&wpB, g_wprojB);
    cudaGetSymbolAddress((void**)&w1B, g_wfc1B);
    cudaGetSymbolAddress((void**)&w2B, g_wfc2B);

    cudaFuncSetAttribute(gemm_h<0>, cudaFuncAttributeMaxDynamicSharedMemorySize, GEMM_SMEM);
    cudaFuncSetAttribute(gemm_h<1>, cudaFuncAttributeMaxDynamicSharedMemorySize, GEMM_SMEM);
    cudaFuncSetAttribute(gemm_h<2>, cudaFuncAttributeMaxDynamicSharedMemorySize, GEMM_SMEM);
    cudaFuncSetAttribute(gemm_h<3>, cudaFuncAttributeMaxDynamicSharedMemorySize, GEMM_SMEM);
    cudaFuncSetAttribute(gemm_h<4>, cudaFuncAttributeMaxDynamicSharedMemorySize, GEMM_SMEM);

    wconv_all<<<1536, 256>>>(w_qkv, w_skip, w_proj, w_fc1, w_fc2,
                             wqB, wsB, wpB, w1B, w2B);

    ln1_kernel<<<4096, 512>>>(x, skip, n1g, n1b, axA, asA);
    gemm_h<0><<<dim3(8, 256), 256, GEMM_SMEM>>>(axA, wqB, b_qkv, nullptr, nullptr, kvb, 1024, 512);
    gemm_h<1><<<dim3(4, 256), 256, GEMM_SMEM>>>(asA, wsB, b_skip, nullptr, nullptr, qb, 512, 512);
    attn_kernel<<<dim3(1024, 4), 256>>>(qb, kvb, relb, asA);
    gemm_h<2><<<dim3(4, 256), 256, GEMM_SMEM>>>(asA, wpB, b_proj, xres, x, nullptr, 512, 512);
    ln2_kernel<<<4096, 512>>>(xres, n2g, n2b, axA);
    gemm_h<3><<<dim3(16, 256), 256, GEMM_SMEM>>>(axA, w1B, b_fc1, nullptr, nullptr, hA, 2048, 512);
    gemm_h<4><<<dim3(4, 256), 256, GEMM_SMEM>>>(hA, w2B, b_fc2, outp, xres, nullptr, 512, 2048);
    (void)in_sizes; (void)n_in; (void)out_size;
}

// round 13
// speedup vs baseline: 1.8211x; 1.8211x over previous
#include <cuda_runtime.h>
#include <cuda_fp16.h>
#include <cstdint>

// ---------------------------------------------------------------------------
// SwinBlock sm_103a round 12:
//  - GEMM: CTA 128x128, 256 thr, 8 warps (2m x 4n), warp 64x32, BK=64,
//    3-stage cp.async, 96KB smem -> 2 CTAs/SM (independent barrier domains).
//  - Attention flash-style, LN, merged wconv: unchanged (1626us version).
// ---------------------------------------------------------------------------

#define TOK   65536
#define CEMB  512
#define FFN   2048

__device__ __half g_axA [(size_t)TOK * CEMB];
__device__ __half g_asA [(size_t)TOK * CEMB];
__device__ __half g_kv  [(size_t)TOK * 1024];
__device__ __half g_q   [(size_t)TOK * CEMB];
__device__ float  g_xres[(size_t)TOK * CEMB];
__device__ __half g_hA  [(size_t)TOK * FFN];
__device__ __half g_wqkvB[1024 * 512];
__device__ __half g_wskipB[512 * 512];
__device__ __half g_wprojB[512 * 512];
__device__ __half g_wfc1B[2048 * 512];
__device__ __half g_wfc2B[512 * 2048];

__device__ __forceinline__ int wt_to_nat(int wt) {
    int n   = wt & 63;
    int win = wt >> 6;
    int wi  = win & 63;
    int b   = win >> 6;
    int hp  = ((wi >> 3) << 3) + (n >> 3);
    int wp  = ((wi & 7)  << 3) + (n & 7);
    int h   = (hp + 4) & 63;
    int w   = (wp + 4) & 63;
    return (b << 12) + (h << 6) + w;
}

__device__ __forceinline__ uint32_t pk2(float a, float b) {
    __half2 h = __floats2half2_rn(a, b);
    return *(uint32_t*)&h;
}

__device__ __forceinline__ void mma16(float c[4], const uint32_t a[4],
                                      uint32_t b0, uint32_t b1) {
    asm volatile(
        "mma.sync.aligned.m16n8k16.row.col.f32.f16.f16.f32 "
        "{%0,%1,%2,%3}, {%4,%5,%6,%7}, {%8,%9}, {%0,%1,%2,%3};\n"
        : "+f"(c[0]), "+f"(c[1]), "+f"(c[2]), "+f"(c[3])
        : "r"(a[0]), "r"(a[1]), "r"(a[2]), "r"(a[3]), "r"(b0), "r"(b1));
}

__device__ __forceinline__ void cpa16(uint32_t dst, const void* src) {
    asm volatile("cp.async.cg.shared.global [%0], [%1], 16;\n" :: "r"(dst), "l"(src));
}
__device__ __forceinline__ void cpa_commit() { asm volatile("cp.async.commit_group;\n"); }
__device__ __forceinline__ void cpa_wait1()  { asm volatile("cp.async.wait_group 1;\n"); }
__device__ __forceinline__ void cpa_wait0()  { asm volatile("cp.async.wait_group 0;\n"); }

// ---------------------------------------------------------------------------
// LayerNorm -> f32 smem staging -> fp16 A-layout write. (unchanged)
// ---------------------------------------------------------------------------
__device__ __forceinline__ void ln_row_st(const float* __restrict__ in,
                                          const float* __restrict__ g,
                                          const float* __restrict__ b,
                                          float* __restrict__ stgrow, int lane) {
    float4 v[4];
    float s = 0.f, sq = 0.f;
#pragma unroll
    for (int j = 0; j < 4; j++) {
        v[j] = *(const float4*)(in + (((j << 5) + lane) << 2));
        s  += v[j].x + v[j].y + v[j].z + v[j].w;
        sq += v[j].x*v[j].x + v[j].y*v[j].y + v[j].z*v[j].z + v[j].w*v[j].w;
    }
#pragma unroll
    for (int o = 16; o; o >>= 1) {
        s  += __shfl_xor_sync(0xffffffffu, s, o);
        sq += __shfl_xor_sync(0xffffffffu, sq, o);
    }
    float mean = s * (1.f / 512.f);
    float var  = sq * (1.f / 512.f) - mean * mean;
    float rstd = rsqrtf(var + 1e-5f);
#pragma unroll
    for (int j = 0; j < 4; j++) {
        int off = (((j << 5) + lane) << 2);
        float4 gg = *(const float4*)(g + off);
        float4 bb = *(const float4*)(b + off);
        stgrow[off + 0] = (v[j].x - mean) * rstd * gg.x + bb.x;
        stgrow[off + 1] = (v[j].y - mean) * rstd * gg.y + bb.y;
        stgrow[off + 2] = (v[j].z - mean) * rstd * gg.z + bb.z;
        stgrow[off + 3] = (v[j].w - mean) * rstd * gg.w + bb.w;
    }
}

__device__ __forceinline__ void stg_writeA16(__half* __restrict__ out, int row0,
                                             const float (*stg)[516]) {
    size_t base = (size_t)(row0 >> 7) * (128 * 512) + (size_t)((row0 >> 4) & 7) * 256;
#pragma unroll
    for (int i = 0; i < 2; i++) {
        int f4  = threadIdx.x + (i << 9);
        int kb16 = f4 >> 5;
        int lane = f4 & 31;
        int lr = lane >> 2, tq = lane & 3;
        int c0 = (kb16 << 4) + (tq << 1);
        uint4 o;
        o.x = pk2(stg[lr    ][c0    ], stg[lr    ][c0 + 1]);
        o.y = pk2(stg[lr + 8][c0    ], stg[lr + 8][c0 + 1]);
        o.z = pk2(stg[lr    ][c0 + 8], stg[lr    ][c0 + 9]);
        o.w = pk2(stg[lr + 8][c0 + 8], stg[lr + 8][c0 + 9]);
        *(uint4*)(out + base + (size_t)kb16 * 2048 + lane * 8) = o;
    }
}

__global__ __launch_bounds__(512) void ln1_kernel(const float* __restrict__ x,
                                                  const float* __restrict__ skip,
                                                  const float* __restrict__ g1,
                                                  const float* __restrict__ b1,
                                                  __half* __restrict__ outxA,
                                                  __half* __restrict__ outsA) {
    __shared__ float stg[16][516];
    int warp = threadIdx.x >> 5, lane = threadIdx.x & 31;
    int row0 = blockIdx.x << 4;
    int nat  = wt_to_nat(row0 + warp);
    ln_row_st(x + (size_t)nat * CEMB, g1, b1, stg[warp], lane);
    __syncthreads();
    stg_writeA16(outxA, row0, stg);
    __syncthreads();
    ln_row_st(skip + (size_t)nat * CEMB, g1, b1, stg[warp], lane);
    __syncthreads();
    stg_writeA16(outsA, row0, stg);
}

__global__ __launch_bounds__(512) void ln2_kernel(const float* __restrict__ xin,
                                                  const float* __restrict__ g2,
                                                  const float* __restrict__ b2,
                                                  __half* __restrict__ outA) {
    __shared__ float stg[16][516];
    int warp = threadIdx.x >> 5, lane = threadIdx.x & 31;
    int row0 = blockIdx.x << 4;
    ln_row_st(xin + (size_t)(row0 + warp) * CEMB, g2, b2, stg[warp], lane);
    __syncthreads();
    stg_writeA16(outA, row0, stg);
}

// merged weight converter (unchanged)
__global__ __launch_bounds__(256) void wconv_all(const float* __restrict__ w0,
                                                 const float* __restrict__ w1,
                                                 const float* __restrict__ w2,
                                                 const float* __restrict__ w3,
                                                 const float* __restrict__ w4,
                                                 __half* __restrict__ o0,
                                                 __half* __restrict__ o1,
                                                 __half* __restrict__ o2,
                                                 __half* __restrict__ o3,
                                                 __half* __restrict__ o4) {
    int id = blockIdx.x * 256 + threadIdx.x;
    const float* w; __half* out; int K; int lid;
    if (id < 65536)       { w = w0; out = o0; K = 512;  lid = id; }
    else if (id < 98304)  { w = w1; out = o1; K = 512;  lid = id - 65536; }
    else if (id < 131072) { w = w2; out = o2; K = 512;  lid = id - 98304; }
    else if (id < 262144) { w = w3; out = o3; K = 512;  lid = id - 131072; }
    else                  { w = w4; out = o4; K = 2048; lid = id - 262144; }
    size_t p0 = (size_t)lid << 3;
    int tp   = K << 7;
    int tile = (int)(p0 / tp);
    int rem  = (int)(p0 - (size_t)tile * tp);
    int kb16 = rem >> 11;
    int rem2 = rem & 2047;
    int ngrp = rem2 >> 8;
    int lane = (rem2 & 255) >> 3;
    int g = lane >> 2, tq = lane & 3;
    int n = (tile << 7) + (ngrp << 4) + g;
    int k = (kb16 << 4) + (tq << 1);
    uint4 o;
    o.x = pk2(w[(size_t)n * K + k],       w[(size_t)n * K + k + 1]);
    o.y = pk2(w[(size_t)n * K + k + 8],   w[(size_t)n * K + k + 9]);
    o.z = pk2(w[(size_t)(n + 8) * K + k],     w[(size_t)(n + 8) * K + k + 1]);
    o.w = pk2(w[(size_t)(n + 8) * K + k + 8], w[(size_t)(n + 8) * K + k + 9]);
    *(uint4*)(out + p0) = o;
}

// ---------------------------------------------------------------------------
// GEMM fp16: CTA 128x128, 256 thr, 8 warps (2m x 4n), warp 64x32, BK=64,
// 3 stages (32KB each), load-at-top. 2 CTAs/SM.
// EPI: 0 +bias->h | 1 *scale->h | 2 +res f32 scatter | 3 gelu->A | 4 +res f32
// ---------------------------------------------------------------------------
#define STG_BYTES 32768
#define GEMM_SMEM (3 * STG_BYTES)

template <int EPI>
__global__ __launch_bounds__(256, 2) void gemm_h(const __half* __restrict__ A,
                                                 const __half* __restrict__ W,
                                                 const float* __restrict__ bias,
                                                 float* __restrict__ out,
                                                 const float* __restrict__ res,
                                                 __half* __restrict__ outh,
                                                 int N, int K) {
    extern __shared__ __align__(16) char smem[];
    const uint32_t sb = (uint32_t)__cvta_generic_to_shared(smem);
    const int tid  = threadIdx.x;
    const int warp = tid >> 5, lane = tid & 31;
    const int wm   = warp >> 2;           // 0..1: 64-row band
    const int wn2  = warp & 3;            // 0..3: 32-col band
    const int g    = lane >> 2, tq = lane & 3;
    const int bm   = blockIdx.y * 128;
    const int bn   = blockIdx.x * 128;

    const size_t aTile = (size_t)(bm >> 7) * 128 * K;
    const size_t bTile = (size_t)(bn >> 7) * 128 * K;

    float acc[4][4][4];
#pragma unroll
    for (int i = 0; i < 4; i++)
#pragma unroll
        for (int j = 0; j < 4; j++)
#pragma unroll
            for (int l = 0; l < 4; l++) acc[i][j][l] = 0.f;

    auto load_stage = [&](int s, int kb) {
        const uint32_t dst = sb + (uint32_t)s * STG_BYTES;
        const size_t ko = (size_t)kb * 8192;
#pragma unroll
        for (int j = 0; j < 4; j++) {            // A: 1024 x 16B
            int f4 = tid + (j << 8);
            cpa16(dst + (uint32_t)f4 * 16, A + aTile + ko + ((size_t)f4 << 3));
        }
#pragma unroll
        for (int j = 0; j < 4; j++) {            // B: 1024 x 16B
            int f4 = tid + (j << 8);
            cpa16(dst + 16384 + (uint32_t)f4 * 16, W + bTile + ko + ((size_t)f4 << 3));
        }
    };

    const int nkb = K >> 6;
    load_stage(0, 0); cpa_commit();
    load_stage(1, 1); cpa_commit();

    const uint32_t aOffW = (uint32_t)wm * 2048 + lane * 16;          // grp base wm*4
    const uint32_t bOffW = 16384 + (uint32_t)wn2 * 1024 + lane * 16; // grp base wn2*2

    int stage = 0;
    for (int kb = 0; kb < nkb; kb++) {
        cpa_wait1();
        __syncthreads();
        if (kb + 2 < nkb) {
            int ns = stage + 2; if (ns >= 3) ns -= 3;
            load_stage(ns, kb + 2);
        }
        cpa_commit();

        const char* st = smem + (size_t)stage * STG_BYTES;
#pragma unroll
        for (int kl = 0; kl < 4; kl++) {
            uint4 a[4], b[2];
#pragma unroll
            for (int mi = 0; mi < 4; mi++)
                a[mi] = *(const uint4*)(st + aOffW + kl * 4096 + mi * 512);
#pragma unroll
            for (int nj = 0; nj < 2; nj++)
                b[nj] = *(const uint4*)(st + bOffW + kl * 4096 + nj * 512);
#pragma unroll
            for (int mi = 0; mi < 4; mi++) {
                uint32_t ar[4] = {a[mi].x, a[mi].y, a[mi].z, a[mi].w};
#pragma unroll
                for (int nj = 0; nj < 2; nj++) {
                    mma16(acc[mi][2 * nj],     ar, b[nj].x, b[nj].y);
                    mma16(acc[mi][2 * nj + 1], ar, b[nj].z, b[nj].w);
                }
            }
        }
        stage++; if (stage >= 3) stage = 0;
    }

    if (EPI == 3) {
        // gelu -> fp16 A-layout. Whole 128x128 tile staged (f32, 67.6KB).
        cpa_wait0();
        __syncthreads();
        float* stg = (float*)smem;   // [128][132]
#pragma unroll
        for (int mi = 0; mi < 4; mi++)
#pragma unroll
            for (int n8 = 0; n8 < 4; n8++) {
                int lc = wn2 * 32 + n8 * 8 + (tq << 1);
                float bv0 = bias[bn + lc], bv1 = bias[bn + lc + 1];
#pragma unroll
                for (int hr = 0; hr < 2; hr++) {
                    int lr = wm * 64 + mi * 16 + g + hr * 8;
                    float v0 = acc[mi][n8][hr * 2]     + bv0;
                    float v1 = acc[mi][n8][hr * 2 + 1] + bv1;
                    const float is2 = 0.70710678118654752f;
                    stg[lr * 132 + lc]     = 0.5f * v0 * (1.f + erff(v0 * is2));
                    stg[lr * 132 + lc + 1] = 0.5f * v1 * (1.f + erff(v1 * is2));
                }
            }
        __syncthreads();
        size_t tbase = (size_t)(bm >> 7) * 128 * N;
#pragma unroll
        for (int i = 0; i < 8; i++) {
            int f4   = tid + (i << 8);       // 0..2047
            int kb16L = f4 >> 8;             // 0..7
            int grp  = (f4 >> 5) & 7;
            int ln2  = f4 & 31;
            int lr   = (grp << 4) + (ln2 >> 2);
            int c0   = (kb16L << 4) + ((ln2 & 3) << 1);
            uint4 o;
            o.x = pk2(stg[lr * 132 + c0],           stg[lr * 132 + c0 + 1]);
            o.y = pk2(stg[(lr + 8) * 132 + c0],     stg[(lr + 8) * 132 + c0 + 1]);
            o.z = pk2(stg[lr * 132 + c0 + 8],       stg[lr * 132 + c0 + 9]);
            o.w = pk2(stg[(lr + 8) * 132 + c0 + 8], stg[(lr + 8) * 132 + c0 + 9]);
            *(uint4*)(outh + tbase + (size_t)((bn >> 4) + kb16L) * 2048
                      + (size_t)grp * 256 + ln2 * 8) = o;
        }
        return;
    }

#pragma unroll
    for (int mi = 0; mi < 4; mi++) {
#pragma unroll
        for (int hr = 0; hr < 2; hr++) {
            int r = bm + wm * 64 + mi * 16 + g + hr * 8;
            size_t obase;
            if (EPI == 2) obase = (size_t)wt_to_nat(r) * CEMB;
            else          obase = (size_t)r * N;
#pragma unroll
            for (int n8 = 0; n8 < 4; n8++) {
                int c = bn + wn2 * 32 + n8 * 8 + (tq << 1);
                float v0 = acc[mi][n8][hr * 2]     + bias[c];
                float v1 = acc[mi][n8][hr * 2 + 1] + bias[c + 1];
                if (EPI == 0) {
                    *(uint32_t*)(outh + obase + c) = pk2(v0, v1);
                } else if (EPI == 1) {
                    const float sc = 0.17677669529663687f;
                    *(uint32_t*)(outh + obase + c) = pk2(v0 * sc, v1 * sc);
                } else {
                    v0 += res[obase + c];
                    v1 += res[obase + c + 1];
                    *(float2*)(out + obase + c) = make_float2(v0, v1);
                }
            }
        }
    }
}

// ---------------------------------------------------------------------------
// Windowed attention, flash-style (unchanged from 1626us kernel).
// ---------------------------------------------------------------------------
__global__ __launch_bounds__(256) void attn_kernel(const __half* __restrict__ q,
                                                   const __half* __restrict__ kv,
                                                   const float* __restrict__ rb,
                                                   __half* __restrict__ outA) {
    __shared__ __align__(16) __half sqh[64][40];
    __shared__ __align__(16) __half skh[64][40];
    __shared__ __align__(16) __half svT[32][72];
    __shared__ float redm[2][64];
    __shared__ float reds[2][64];
    __shared__ float soP[2][64][36];

    const int tid  = threadIdx.x;
    const int warp = tid >> 5, lane = tid & 31;
    const int g    = lane >> 2, tq = lane & 3;
    const int wm   = warp >> 1;
    const int wn   = warp & 1;
    const int tn0  = wm << 4;
    const int n00  = wn << 5;
    const int win  = blockIdx.x;
    const int wi   = win & 63;
    const int wr   = wi >> 3, wc = wi & 7;
    const int base = win << 6;
    const int h0   = blockIdx.y << 2;
    const size_t tbase = (size_t)(win >> 1) * (128 * 512);
    const int grpBase = (win & 1) * 4;

    for (int h = h0; h < h0 + 4; h++) {
        {
            int rown = tid >> 2;
            int ch   = tid & 3;
            *(uint4*)&sqh[rown][ch << 3] =
                *(const uint4*)(q  + (size_t)(base + rown) * 512  + h * 32 + (ch << 3));
            *(uint4*)&skh[rown][ch << 3] =
                *(const uint4*)(kv + (size_t)(base + rown) * 1024 + h * 32 + (ch << 3));
            union { uint4 u; __half hs[8]; } vv;
            vv.u = *(const uint4*)(kv + (size_t)(base + rown) * 1024 + 512 + h * 32 + (ch << 3));
#pragma unroll
            for (int dd = 0; dd < 8; dd++)
                svT[(ch << 3) + dd][rown] = vv.hs[dd];
        }
        __syncthreads();

        float s[4][4];
        {
            uint32_t aF[2][4];
#pragma unroll
            for (int ks = 0; ks < 2; ks++) {
                int k0 = ks << 4;
                aF[ks][0] = *(const uint32_t*)&sqh[tn0 + g    ][(tq << 1) + k0];
                aF[ks][1] = *(const uint32_t*)&sqh[tn0 + g + 8][(tq << 1) + k0];
                aF[ks][2] = *(const uint32_t*)&sqh[tn0 + g    ][(tq << 1) + 8 + k0];
                aF[ks][3] = *(const uint32_t*)&sqh[tn0 + g + 8][(tq << 1) + 8 + k0];
            }
#pragma unroll
            for (int nj = 0; nj < 4; nj++) {
#pragma unroll
                for (int l = 0; l < 4; l++) s[nj][l] = 0.f;
#pragma unroll
                for (int ks = 0; ks < 2; ks++) {
                    int k0 = ks << 4;
                    uint32_t b0 = *(const uint32_t*)&skh[n00 + (nj << 3) + g][(tq << 1) + k0];
                    uint32_t b1 = *(const uint32_t*)&skh[n00 + (nj << 3) + g][(tq << 1) + 8 + k0];
                    mma16(s[nj], aF[ks], b0, b1);
                }
            }
#pragma unroll
            for (int hr = 0; hr < 2; hr++) {
                int n = tn0 + g + (hr << 3);
                int cn = 15 * (n >> 3) + (n & 7);
                int rhn = (wr == 7) ? (((n >> 3) < 4) ? 1 : 2) : 0;
                int rwn = (wc == 7) ? (((n & 7)  < 4) ? 1 : 2) : 0;
                int regn = rhn * 3 + rwn;
#pragma unroll
                for (int nj = 0; nj < 4; nj++)
#pragma unroll
                    for (int cc = 0; cc < 2; cc++) {
                        int m = n00 + (nj << 3) + (tq << 1) + cc;
                        int m2 = 63 - m;
                        int cm = 15 * (m2 >> 3) + (m2 & 7);
                        float bv = rb[(cn + cm) * 16 + h];
                        int rhm = (wr == 7) ? (((m >> 3) < 4) ? 1 : 2) : 0;
                        int rwm = (wc == 7) ? (((m & 7)  < 4) ? 1 : 2) : 0;
                        float msk = ((rhm * 3 + rwm) != regn) ? -100.f : 0.f;
                        s[nj][hr * 2 + cc] += bv + msk;
                    }
            }
        }

        float e[4][4], scl0, scl1;
        {
            float mx0 = -1e30f, mx1 = -1e30f;
#pragma unroll
            for (int nj = 0; nj < 4; nj++) {
                mx0 = fmaxf(mx0, fmaxf(s[nj][0], s[nj][1]));
                mx1 = fmaxf(mx1, fmaxf(s[nj][2], s[nj][3]));
            }
            mx0 = fmaxf(mx0, __shfl_xor_sync(0xffffffffu, mx0, 1));
            mx0 = fmaxf(mx0, __shfl_xor_sync(0xffffffffu, mx0, 2));
            mx1 = fmaxf(mx1, __shfl_xor_sync(0xffffffffu, mx1, 1));
            mx1 = fmaxf(mx1, __shfl_xor_sync(0xffffffffu, mx1, 2));
            float sm0 = 0.f, sm1 = 0.f;
#pragma unroll
            for (int nj = 0; nj < 4; nj++) {
                e[nj][0] = expf(s[nj][0] - mx0);
                e[nj][1] = expf(s[nj][1] - mx0);
                e[nj][2] = expf(s[nj][2] - mx1);
                e[nj][3] = expf(s[nj][3] - mx1);
                sm0 += e[nj][0] + e[nj][1];
                sm1 += e[nj][2] + e[nj][3];
            }
            sm0 += __shfl_xor_sync(0xffffffffu, sm0, 1);
            sm0 += __shfl_xor_sync(0xffffffffu, sm0, 2);
            sm1 += __shfl_xor_sync(0xffffffffu, sm1, 1);
            sm1 += __shfl_xor_sync(0xffffffffu, sm1, 2);
            if (tq == 0) {
                redm[wn][tn0 + g]     = mx0;  reds[wn][tn0 + g]     = sm0;
                redm[wn][tn0 + g + 8] = mx1;  reds[wn][tn0 + g + 8] = sm1;
            }
            __syncthreads();
            int r0 = tn0 + g, r1 = tn0 + g + 8;
            float Ma = fmaxf(redm[0][r0], redm[1][r0]);
            float den0 = reds[0][r0] * expf(redm[0][r0] - Ma)
                       + reds[1][r0] * expf(redm[1][r0] - Ma);
            scl0 = expf(mx0 - Ma) / den0;
            float Mb = fmaxf(redm[0][r1], redm[1][r1]);
            float den1 = reds[0][r1] * expf(redm[0][r1] - Mb)
                       + reds[1][r1] * expf(redm[1][r1] - Mb);
            scl1 = expf(mx1 - Mb) / den1;
        }

        uint32_t aP[2][4];
#pragma unroll
        for (int kj = 0; kj < 2; kj++) {
            int njl = kj * 2, njh = kj * 2 + 1;
            aP[kj][0] = pk2(e[njl][0] * scl0, e[njl][1] * scl0);
            aP[kj][1] = pk2(e[njl][2] * scl1, e[njl][3] * scl1);
            aP[kj][2] = pk2(e[njh][0] * scl0, e[njh][1] * scl0);
            aP[kj][3] = pk2(e[njh][2] * scl1, e[njh][3] * scl1);
        }

        float accO[4][4];
#pragma unroll
        for (int dj = 0; dj < 4; dj++)
#pragma unroll
            for (int l = 0; l < 4; l++) accO[dj][l] = 0.f;
#pragma unroll
        for (int kj = 0; kj < 2; kj++) {
            int kbase = n00 + (kj << 4) + (tq << 1);
#pragma unroll
            for (int dj = 0; dj < 4; dj++) {
                uint32_t b0 = *(const uint32_t*)&svT[(dj << 3) + g][kbase];
                uint32_t b1 = *(const uint32_t*)&svT[(dj << 3) + g][kbase + 8];
                mma16(accO[dj], aP[kj], b0, b1);
            }
        }
#pragma unroll
        for (int dj = 0; dj < 4; dj++)
#pragma unroll
            for (int hr = 0; hr < 2; hr++) {
                int rr = tn0 + g + (hr << 3);
                int dd = (dj << 3) + (tq << 1);
                *(float2*)&soP[wn][rr][dd] =
                    make_float2(accO[dj][hr * 2], accO[dj][hr * 2 + 1]);
            }
        __syncthreads();

        {
            int kb16L = tid >> 7;
            int grpL  = (tid >> 5) & 3;
            int ln2   = tid & 31;
            int lr    = (grpL << 4) + (ln2 >> 2);
            int c0    = (kb16L << 4) + ((ln2 & 3) << 1);
            uint4 o;
            o.x = pk2(soP[0][lr][c0]         + soP[1][lr][c0],
                      soP[0][lr][c0 + 1]     + soP[1][lr][c0 + 1]);
            o.y = pk2(soP[0][lr + 8][c0]     + soP[1][lr + 8][c0],
                      soP[0][lr + 8][c0 + 1] + soP[1][lr + 8][c0 + 1]);
            o.z = pk2(soP[0][lr][c0 + 8]     + soP[1][lr][c0 + 8],
                      soP[0][lr][c0 + 9]     + soP[1][lr][c0 + 9]);
            o.w = pk2(soP[0][lr + 8][c0 + 8] + soP[1][lr + 8][c0 + 8],
                      soP[0][lr + 8][c0 + 9] + soP[1][lr + 8][c0 + 9]);
            *(uint4*)(outA + tbase + (size_t)(2 * h + kb16L) * 2048
                      + (size_t)(grpBase + grpL) * 256 + ln2 * 8) = o;
        }
        __syncthreads();
    }
}

// ---------------------------------------------------------------------------
extern "C" void kernel_launch(void* const* d_in, const int* in_sizes, int n_in,
                              void* d_out, int out_size) {
    const float* x      = (const float*)d_in[0];
    const float* skip   = (const float*)d_in[1];
    const float* n1g    = (const float*)d_in[2];
    const float* n1b    = (const float*)d_in[3];
    const float* w_qkv  = (const float*)d_in[4];
    const float* b_qkv  = (const float*)d_in[5];
    const float* w_skip = (const float*)d_in[6];
    const float* b_skip = (const float*)d_in[7];
    const float* relb   = (const float*)d_in[8];
    const float* w_proj = (const float*)d_in[9];
    const float* b_proj = (const float*)d_in[10];
    const float* n2g    = (const float*)d_in[11];
    const float* n2b    = (const float*)d_in[12];
    const float* w_fc1  = (const float*)d_in[13];
    const float* b_fc1  = (const float*)d_in[14];
    const float* w_fc2  = (const float*)d_in[15];
    const float* b_fc2  = (const float*)d_in[16];
    float* outp = (float*)d_out;

    __half *axA, *asA, *hA, *wqB, *wsB, *wpB, *w1B, *w2B, *kvb, *qb;
    float *xres;
    cudaGetSymbolAddress((void**)&axA, g_axA);
    cudaGetSymbolAddress((void**)&asA, g_asA);
    cudaGetSymbolAddress((void**)&kvb, g_kv);
    cudaGetSymbolAddress((void**)&qb,  g_q);
    cudaGetSymbolAddress((void**)&xres, g_xres);
    cudaGetSymbolAddress((void**)&hA,  g_hA);
    cudaGetSymbolAddress((void**)&wqB, g_wqkvB);
    cudaGetSymbolAddress((void**)&wsB, g_wskipB);
    cudaGetSymbolAddress((void**)&wpB, g_wprojB);
    cudaGetSymbolAddress((void**)&w1B, g_wfc1B);
    cudaGetSymbolAddress((void**)&w2B, g_wfc2B);

    cudaFuncSetAttribute(gemm_h<0>, cudaFuncAttributeMaxDynamicSharedMemorySize, GEMM_SMEM);
    cudaFuncSetAttribute(gemm_h<1>, cudaFuncAttributeMaxDynamicSharedMemorySize, GEMM_SMEM);
    cudaFuncSetAttribute(gemm_h<2>, cudaFuncAttributeMaxDynamicSharedMemorySize, GEMM_SMEM);
    cudaFuncSetAttribute(gemm_h<3>, cudaFuncAttributeMaxDynamicSharedMemorySize, GEMM_SMEM);
    cudaFuncSetAttribute(gemm_h<4>, cudaFuncAttributeMaxDynamicSharedMemorySize, GEMM_SMEM);

    wconv_all<<<1536, 256>>>(w_qkv, w_skip, w_proj, w_fc1, w_fc2,
                             wqB, wsB, wpB, w1B, w2B);

    ln1_kernel<<<4096, 512>>>(x, skip, n1g, n1b, axA, asA);
    gemm_h<0><<<dim3(8, 512), 256, GEMM_SMEM>>>(axA, wqB, b_qkv, nullptr, nullptr, kvb, 1024, 512);
    gemm_h<1><<<dim3(4, 512), 256, GEMM_SMEM>>>(asA, wsB, b_skip, nullptr, nullptr, qb, 512, 512);
    attn_kernel<<<dim3(1024, 4), 256>>>(qb, kvb, relb, asA);
    gemm_h<2><<<dim3(4, 512), 256, GEMM_SMEM>>>(asA, wpB, b_proj, xres, x, nullptr, 512, 512);
    ln2_kernel<<<4096, 512>>>(xres, n2g, n2b, axA);
    gemm_h<3><<<dim3(16, 512), 256, GEMM_SMEM>>>(axA, w1B, b_fc1, nullptr, nullptr, hA, 2048, 512);
    gemm_h<4><<<dim3(4, 512), 256, GEMM_SMEM>>>(hA, w2B, b_fc2, outp, xres, nullptr, 512, 2048);
    (void)in_sizes; (void)n_in; (void)out_size;
}

// round 14
// speedup vs baseline: 1.8409x; 1.0109x over previous
#include <cuda_runtime.h>
#include <cuda_fp16.h>
#include <cstdint>

// ---------------------------------------------------------------------------
// SwinBlock sm_103a round 13:
//  - GEMM: CTA 128x128, 256 thr, warp 64x32, BK=64, 3-stage, 2 CTAs/SM
//    (unchanged 1425us version).
//  - Attention: ONE (window, head) PER CTA  (grid 1024 x 16, no head loop).
//  - LN, merged wconv: unchanged.
// ---------------------------------------------------------------------------

#define TOK   65536
#define CEMB  512
#define FFN   2048

__device__ __half g_axA [(size_t)TOK * CEMB];
__device__ __half g_asA [(size_t)TOK * CEMB];
__device__ __half g_kv  [(size_t)TOK * 1024];
__device__ __half g_q   [(size_t)TOK * CEMB];
__device__ float  g_xres[(size_t)TOK * CEMB];
__device__ __half g_hA  [(size_t)TOK * FFN];
__device__ __half g_wqkvB[1024 * 512];
__device__ __half g_wskipB[512 * 512];
__device__ __half g_wprojB[512 * 512];
__device__ __half g_wfc1B[2048 * 512];
__device__ __half g_wfc2B[512 * 2048];

__device__ __forceinline__ int wt_to_nat(int wt) {
    int n   = wt & 63;
    int win = wt >> 6;
    int wi  = win & 63;
    int b   = win >> 6;
    int hp  = ((wi >> 3) << 3) + (n >> 3);
    int wp  = ((wi & 7)  << 3) + (n & 7);
    int h   = (hp + 4) & 63;
    int w   = (wp + 4) & 63;
    return (b << 12) + (h << 6) + w;
}

__device__ __forceinline__ uint32_t pk2(float a, float b) {
    __half2 h = __floats2half2_rn(a, b);
    return *(uint32_t*)&h;
}

__device__ __forceinline__ void mma16(float c[4], const uint32_t a[4],
                                      uint32_t b0, uint32_t b1) {
    asm volatile(
        "mma.sync.aligned.m16n8k16.row.col.f32.f16.f16.f32 "
        "{%0,%1,%2,%3}, {%4,%5,%6,%7}, {%8,%9}, {%0,%1,%2,%3};\n"
        : "+f"(c[0]), "+f"(c[1]), "+f"(c[2]), "+f"(c[3])
        : "r"(a[0]), "r"(a[1]), "r"(a[2]), "r"(a[3]), "r"(b0), "r"(b1));
}

__device__ __forceinline__ void cpa16(uint32_t dst, const void* src) {
    asm volatile("cp.async.cg.shared.global [%0], [%1], 16;\n" :: "r"(dst), "l"(src));
}
__device__ __forceinline__ void cpa_commit() { asm volatile("cp.async.commit_group;\n"); }
__device__ __forceinline__ void cpa_wait1()  { asm volatile("cp.async.wait_group 1;\n"); }
__device__ __forceinline__ void cpa_wait0()  { asm volatile("cp.async.wait_group 0;\n"); }

// ---------------------------------------------------------------------------
// LayerNorm -> f32 smem staging -> fp16 A-layout write. (unchanged)
// ---------------------------------------------------------------------------
__device__ __forceinline__ void ln_row_st(const float* __restrict__ in,
                                          const float* __restrict__ g,
                                          const float* __restrict__ b,
                                          float* __restrict__ stgrow, int lane) {
    float4 v[4];
    float s = 0.f, sq = 0.f;
#pragma unroll
    for (int j = 0; j < 4; j++) {
        v[j] = *(const float4*)(in + (((j << 5) + lane) << 2));
        s  += v[j].x + v[j].y + v[j].z + v[j].w;
        sq += v[j].x*v[j].x + v[j].y*v[j].y + v[j].z*v[j].z + v[j].w*v[j].w;
    }
#pragma unroll
    for (int o = 16; o; o >>= 1) {
        s  += __shfl_xor_sync(0xffffffffu, s, o);
        sq += __shfl_xor_sync(0xffffffffu, sq, o);
    }
    float mean = s * (1.f / 512.f);
    float var  = sq * (1.f / 512.f) - mean * mean;
    float rstd = rsqrtf(var + 1e-5f);
#pragma unroll
    for (int j = 0; j < 4; j++) {
        int off = (((j << 5) + lane) << 2);
        float4 gg = *(const float4*)(g + off);
        float4 bb = *(const float4*)(b + off);
        stgrow[off + 0] = (v[j].x - mean) * rstd * gg.x + bb.x;
        stgrow[off + 1] = (v[j].y - mean) * rstd * gg.y + bb.y;
        stgrow[off + 2] = (v[j].z - mean) * rstd * gg.z + bb.z;
        stgrow[off + 3] = (v[j].w - mean) * rstd * gg.w + bb.w;
    }
}

__device__ __forceinline__ void stg_writeA16(__half* __restrict__ out, int row0,
                                             const float (*stg)[516]) {
    size_t base = (size_t)(row0 >> 7) * (128 * 512) + (size_t)((row0 >> 4) & 7) * 256;
#pragma unroll
    for (int i = 0; i < 2; i++) {
        int f4  = threadIdx.x + (i << 9);
        int kb16 = f4 >> 5;
        int lane = f4 & 31;
        int lr = lane >> 2, tq = lane & 3;
        int c0 = (kb16 << 4) + (tq << 1);
        uint4 o;
        o.x = pk2(stg[lr    ][c0    ], stg[lr    ][c0 + 1]);
        o.y = pk2(stg[lr + 8][c0    ], stg[lr + 8][c0 + 1]);
        o.z = pk2(stg[lr    ][c0 + 8], stg[lr    ][c0 + 9]);
        o.w = pk2(stg[lr + 8][c0 + 8], stg[lr + 8][c0 + 9]);
        *(uint4*)(out + base + (size_t)kb16 * 2048 + lane * 8) = o;
    }
}

__global__ __launch_bounds__(512) void ln1_kernel(const float* __restrict__ x,
                                                  const float* __restrict__ skip,
                                                  const float* __restrict__ g1,
                                                  const float* __restrict__ b1,
                                                  __half* __restrict__ outxA,
                                                  __half* __restrict__ outsA) {
    __shared__ float stg[16][516];
    int warp = threadIdx.x >> 5, lane = threadIdx.x & 31;
    int row0 = blockIdx.x << 4;
    int nat  = wt_to_nat(row0 + warp);
    ln_row_st(x + (size_t)nat * CEMB, g1, b1, stg[warp], lane);
    __syncthreads();
    stg_writeA16(outxA, row0, stg);
    __syncthreads();
    ln_row_st(skip + (size_t)nat * CEMB, g1, b1, stg[warp], lane);
    __syncthreads();
    stg_writeA16(outsA, row0, stg);
}

__global__ __launch_bounds__(512) void ln2_kernel(const float* __restrict__ xin,
                                                  const float* __restrict__ g2,
                                                  const float* __restrict__ b2,
                                                  __half* __restrict__ outA) {
    __shared__ float stg[16][516];
    int warp = threadIdx.x >> 5, lane = threadIdx.x & 31;
    int row0 = blockIdx.x << 4;
    ln_row_st(xin + (size_t)(row0 + warp) * CEMB, g2, b2, stg[warp], lane);
    __syncthreads();
    stg_writeA16(outA, row0, stg);
}

// merged weight converter (unchanged)
__global__ __launch_bounds__(256) void wconv_all(const float* __restrict__ w0,
                                                 const float* __restrict__ w1,
                                                 const float* __restrict__ w2,
                                                 const float* __restrict__ w3,
                                                 const float* __restrict__ w4,
                                                 __half* __restrict__ o0,
                                                 __half* __restrict__ o1,
                                                 __half* __restrict__ o2,
                                                 __half* __restrict__ o3,
                                                 __half* __restrict__ o4) {
    int id = blockIdx.x * 256 + threadIdx.x;
    const float* w; __half* out; int K; int lid;
    if (id < 65536)       { w = w0; out = o0; K = 512;  lid = id; }
    else if (id < 98304)  { w = w1; out = o1; K = 512;  lid = id - 65536; }
    else if (id < 131072) { w = w2; out = o2; K = 512;  lid = id - 98304; }
    else if (id < 262144) { w = w3; out = o3; K = 512;  lid = id - 131072; }
    else                  { w = w4; out = o4; K = 2048; lid = id - 262144; }
    size_t p0 = (size_t)lid << 3;
    int tp   = K << 7;
    int tile = (int)(p0 / tp);
    int rem  = (int)(p0 - (size_t)tile * tp);
    int kb16 = rem >> 11;
    int rem2 = rem & 2047;
    int ngrp = rem2 >> 8;
    int lane = (rem2 & 255) >> 3;
    int g = lane >> 2, tq = lane & 3;
    int n = (tile << 7) + (ngrp << 4) + g;
    int k = (kb16 << 4) + (tq << 1);
    uint4 o;
    o.x = pk2(w[(size_t)n * K + k],       w[(size_t)n * K + k + 1]);
    o.y = pk2(w[(size_t)n * K + k + 8],   w[(size_t)n * K + k + 9]);
    o.z = pk2(w[(size_t)(n + 8) * K + k],     w[(size_t)(n + 8) * K + k + 1]);
    o.w = pk2(w[(size_t)(n + 8) * K + k + 8], w[(size_t)(n + 8) * K + k + 9]);
    *(uint4*)(out + p0) = o;
}

// ---------------------------------------------------------------------------
// GEMM fp16: CTA 128x128, 256 thr, 8 warps (2m x 4n), warp 64x32, BK=64,
// 3 stages, 2 CTAs/SM. (unchanged 1425us version)
// ---------------------------------------------------------------------------
#define STG_BYTES 32768
#define GEMM_SMEM (3 * STG_BYTES)

template <int EPI>
__global__ __launch_bounds__(256, 2) void gemm_h(const __half* __restrict__ A,
                                                 const __half* __restrict__ W,
                                                 const float* __restrict__ bias,
                                                 float* __restrict__ out,
                                                 const float* __restrict__ res,
                                                 __half* __restrict__ outh,
                                                 int N, int K) {
    extern __shared__ __align__(16) char smem[];
    const uint32_t sb = (uint32_t)__cvta_generic_to_shared(smem);
    const int tid  = threadIdx.x;
    const int warp = tid >> 5, lane = tid & 31;
    const int wm   = warp >> 2;
    const int wn2  = warp & 3;
    const int g    = lane >> 2, tq = lane & 3;
    const int bm   = blockIdx.y * 128;
    const int bn   = blockIdx.x * 128;

    const size_t aTile = (size_t)(bm >> 7) * 128 * K;
    const size_t bTile = (size_t)(bn >> 7) * 128 * K;

    float acc[4][4][4];
#pragma unroll
    for (int i = 0; i < 4; i++)
#pragma unroll
        for (int j = 0; j < 4; j++)
#pragma unroll
            for (int l = 0; l < 4; l++) acc[i][j][l] = 0.f;

    auto load_stage = [&](int s, int kb) {
        const uint32_t dst = sb + (uint32_t)s * STG_BYTES;
        const size_t ko = (size_t)kb * 8192;
#pragma unroll
        for (int j = 0; j < 4; j++) {
            int f4 = tid + (j << 8);
            cpa16(dst + (uint32_t)f4 * 16, A + aTile + ko + ((size_t)f4 << 3));
        }
#pragma unroll
        for (int j = 0; j < 4; j++) {
            int f4 = tid + (j << 8);
            cpa16(dst + 16384 + (uint32_t)f4 * 16, W + bTile + ko + ((size_t)f4 << 3));
        }
    };

    const int nkb = K >> 6;
    load_stage(0, 0); cpa_commit();
    load_stage(1, 1); cpa_commit();

    const uint32_t aOffW = (uint32_t)wm * 2048 + lane * 16;
    const uint32_t bOffW = 16384 + (uint32_t)wn2 * 1024 + lane * 16;

    int stage = 0;
    for (int kb = 0; kb < nkb; kb++) {
        cpa_wait1();
        __syncthreads();
        if (kb + 2 < nkb) {
            int ns = stage + 2; if (ns >= 3) ns -= 3;
            load_stage(ns, kb + 2);
        }
        cpa_commit();

        const char* st = smem + (size_t)stage * STG_BYTES;
#pragma unroll
        for (int kl = 0; kl < 4; kl++) {
            uint4 a[4], b[2];
#pragma unroll
            for (int mi = 0; mi < 4; mi++)
                a[mi] = *(const uint4*)(st + aOffW + kl * 4096 + mi * 512);
#pragma unroll
            for (int nj = 0; nj < 2; nj++)
                b[nj] = *(const uint4*)(st + bOffW + kl * 4096 + nj * 512);
#pragma unroll
            for (int mi = 0; mi < 4; mi++) {
                uint32_t ar[4] = {a[mi].x, a[mi].y, a[mi].z, a[mi].w};
#pragma unroll
                for (int nj = 0; nj < 2; nj++) {
                    mma16(acc[mi][2 * nj],     ar, b[nj].x, b[nj].y);
                    mma16(acc[mi][2 * nj + 1], ar, b[nj].z, b[nj].w);
                }
            }
        }
        stage++; if (stage >= 3) stage = 0;
    }

    if (EPI == 3) {
        cpa_wait0();
        __syncthreads();
        float* stg = (float*)smem;   // [128][132]
#pragma unroll
        for (int mi = 0; mi < 4; mi++)
#pragma unroll
            for (int n8 = 0; n8 < 4; n8++) {
                int lc = wn2 * 32 + n8 * 8 + (tq << 1);
                float bv0 = bias[bn + lc], bv1 = bias[bn + lc + 1];
#pragma unroll
                for (int hr = 0; hr < 2; hr++) {
                    int lr = wm * 64 + mi * 16 + g + hr * 8;
                    float v0 = acc[mi][n8][hr * 2]     + bv0;
                    float v1 = acc[mi][n8][hr * 2 + 1] + bv1;
                    const float is2 = 0.70710678118654752f;
                    stg[lr * 132 + lc]     = 0.5f * v0 * (1.f + erff(v0 * is2));
                    stg[lr * 132 + lc + 1] = 0.5f * v1 * (1.f + erff(v1 * is2));
                }
            }
        __syncthreads();
        size_t tbase = (size_t)(bm >> 7) * 128 * N;
#pragma unroll
        for (int i = 0; i < 8; i++) {
            int f4   = tid + (i << 8);
            int kb16L = f4 >> 8;
            int grp  = (f4 >> 5) & 7;
            int ln2  = f4 & 31;
            int lr   = (grp << 4) + (ln2 >> 2);
            int c0   = (kb16L << 4) + ((ln2 & 3) << 1);
            uint4 o;
            o.x = pk2(stg[lr * 132 + c0],           stg[lr * 132 + c0 + 1]);
            o.y = pk2(stg[(lr + 8) * 132 + c0],     stg[(lr + 8) * 132 + c0 + 1]);
            o.z = pk2(stg[lr * 132 + c0 + 8],       stg[lr * 132 + c0 + 9]);
            o.w = pk2(stg[(lr + 8) * 132 + c0 + 8], stg[(lr + 8) * 132 + c0 + 9]);
            *(uint4*)(outh + tbase + (size_t)((bn >> 4) + kb16L) * 2048
                      + (size_t)grp * 256 + ln2 * 8) = o;
        }
        return;
    }

#pragma unroll
    for (int mi = 0; mi < 4; mi++) {
#pragma unroll
        for (int hr = 0; hr < 2; hr++) {
            int r = bm + wm * 64 + mi * 16 + g + hr * 8;
            size_t obase;
            if (EPI == 2) obase = (size_t)wt_to_nat(r) * CEMB;
            else          obase = (size_t)r * N;
#pragma unroll
            for (int n8 = 0; n8 < 4; n8++) {
                int c = bn + wn2 * 32 + n8 * 8 + (tq << 1);
                float v0 = acc[mi][n8][hr * 2]     + bias[c];
                float v1 = acc[mi][n8][hr * 2 + 1] + bias[c + 1];
                if (EPI == 0) {
                    *(uint32_t*)(outh + obase + c) = pk2(v0, v1);
                } else if (EPI == 1) {
                    const float sc = 0.17677669529663687f;
                    *(uint32_t*)(outh + obase + c) = pk2(v0 * sc, v1 * sc);
                } else {
                    v0 += res[obase + c];
                    v1 += res[obase + c + 1];
                    *(float2*)(out + obase + c) = make_float2(v0, v1);
                }
            }
        }
    }
}

// ---------------------------------------------------------------------------
// Windowed attention, flash-style, ONE (window, head) PER CTA.
// grid (1024, 16), 256 threads (8 warps: 4 row-bands x 2 key-bands).
// ---------------------------------------------------------------------------
__global__ __launch_bounds__(256) void attn_kernel(const __half* __restrict__ q,
                                                   const __half* __restrict__ kv,
                                                   const float* __restrict__ rb,
                                                   __half* __restrict__ outA) {
    __shared__ __align__(16) __half sqh[64][40];
    __shared__ __align__(16) __half skh[64][40];
    __shared__ __align__(16) __half svT[32][72];
    __shared__ float redm[2][64];
    __shared__ float reds[2][64];
    __shared__ float soP[2][64][36];

    const int tid  = threadIdx.x;
    const int warp = tid >> 5, lane = tid & 31;
    const int g    = lane >> 2, tq = lane & 3;
    const int wm   = warp >> 1;
    const int wn   = warp & 1;
    const int tn0  = wm << 4;
    const int n00  = wn << 5;
    const int win  = blockIdx.x;
    const int h    = blockIdx.y;
    const int wi   = win & 63;
    const int wr   = wi >> 3, wc = wi & 7;
    const int base = win << 6;
    const size_t tbase = (size_t)(win >> 1) * (128 * 512);
    const int grpBase = (win & 1) * 4;

    // ---- load Q, K, V^T
    {
        int rown = tid >> 2;
        int ch   = tid & 3;
        *(uint4*)&sqh[rown][ch << 3] =
            *(const uint4*)(q  + (size_t)(base + rown) * 512  + h * 32 + (ch << 3));
        *(uint4*)&skh[rown][ch << 3] =
            *(const uint4*)(kv + (size_t)(base + rown) * 1024 + h * 32 + (ch << 3));
        union { uint4 u; __half hs[8]; } vv;
        vv.u = *(const uint4*)(kv + (size_t)(base + rown) * 1024 + 512 + h * 32 + (ch << 3));
#pragma unroll
        for (int dd = 0; dd < 8; dd++)
            svT[(ch << 3) + dd][rown] = vv.hs[dd];
    }
    __syncthreads();

    // ---- S = Q K^T (+bias+mask), in registers
    float s[4][4];
    {
        uint32_t aF[2][4];
#pragma unroll
        for (int ks = 0; ks < 2; ks++) {
            int k0 = ks << 4;
            aF[ks][0] = *(const uint32_t*)&sqh[tn0 + g    ][(tq << 1) + k0];
            aF[ks][1] = *(const uint32_t*)&sqh[tn0 + g + 8][(tq << 1) + k0];
            aF[ks][2] = *(const uint32_t*)&sqh[tn0 + g    ][(tq << 1) + 8 + k0];
            aF[ks][3] = *(const uint32_t*)&sqh[tn0 + g + 8][(tq << 1) + 8 + k0];
        }
#pragma unroll
        for (int nj = 0; nj < 4; nj++) {
#pragma unroll
            for (int l = 0; l < 4; l++) s[nj][l] = 0.f;
#pragma unroll
            for (int ks = 0; ks < 2; ks++) {
                int k0 = ks << 4;
                uint32_t b0 = *(const uint32_t*)&skh[n00 + (nj << 3) + g][(tq << 1) + k0];
                uint32_t b1 = *(const uint32_t*)&skh[n00 + (nj << 3) + g][(tq << 1) + 8 + k0];
                mma16(s[nj], aF[ks], b0, b1);
            }
        }
#pragma unroll
        for (int hr = 0; hr < 2; hr++) {
            int n = tn0 + g + (hr << 3);
            int cn = 15 * (n >> 3) + (n & 7);
            int rhn = (wr == 7) ? (((n >> 3) < 4) ? 1 : 2) : 0;
            int rwn = (wc == 7) ? (((n & 7)  < 4) ? 1 : 2) : 0;
            int regn = rhn * 3 + rwn;
#pragma unroll
            for (int nj = 0; nj < 4; nj++)
#pragma unroll
                for (int cc = 0; cc < 2; cc++) {
                    int m = n00 + (nj << 3) + (tq << 1) + cc;
                    int m2 = 63 - m;
                    int cm = 15 * (m2 >> 3) + (m2 & 7);
                    float bv = rb[(cn + cm) * 16 + h];
                    int rhm = (wr == 7) ? (((m >> 3) < 4) ? 1 : 2) : 0;
                    int rwm = (wc == 7) ? (((m & 7)  < 4) ? 1 : 2) : 0;
                    float msk = ((rhm * 3 + rwm) != regn) ? -100.f : 0.f;
                    s[nj][hr * 2 + cc] += bv + msk;
                }
        }
    }

    // ---- two-level softmax
    float e[4][4], scl0, scl1;
    {
        float mx0 = -1e30f, mx1 = -1e30f;
#pragma unroll
        for (int nj = 0; nj < 4; nj++) {
            mx0 = fmaxf(mx0, fmaxf(s[nj][0], s[nj][1]));
            mx1 = fmaxf(mx1, fmaxf(s[nj][2], s[nj][3]));
        }
        mx0 = fmaxf(mx0, __shfl_xor_sync(0xffffffffu, mx0, 1));
        mx0 = fmaxf(mx0, __shfl_xor_sync(0xffffffffu, mx0, 2));
        mx1 = fmaxf(mx1, __shfl_xor_sync(0xffffffffu, mx1, 1));
        mx1 = fmaxf(mx1, __shfl_xor_sync(0xffffffffu, mx1, 2));
        float sm0 = 0.f, sm1 = 0.f;
#pragma unroll
        for (int nj = 0; nj < 4; nj++) {
            e[nj][0] = expf(s[nj][0] - mx0);
            e[nj][1] = expf(s[nj][1] - mx0);
            e[nj][2] = expf(s[nj][2] - mx1);
            e[nj][3] = expf(s[nj][3] - mx1);
            sm0 += e[nj][0] + e[nj][1];
            sm1 += e[nj][2] + e[nj][3];
        }
        sm0 += __shfl_xor_sync(0xffffffffu, sm0, 1);
        sm0 += __shfl_xor_sync(0xffffffffu, sm0, 2);
        sm1 += __shfl_xor_sync(0xffffffffu, sm1, 1);
        sm1 += __shfl_xor_sync(0xffffffffu, sm1, 2);
        if (tq == 0) {
            redm[wn][tn0 + g]     = mx0;  reds[wn][tn0 + g]     = sm0;
            redm[wn][tn0 + g + 8] = mx1;  reds[wn][tn0 + g + 8] = sm1;
        }
        __syncthreads();
        int r0 = tn0 + g, r1 = tn0 + g + 8;
        float Ma = fmaxf(redm[0][r0], redm[1][r0]);
        float den0 = reds[0][r0] * expf(redm[0][r0] - Ma)
                   + reds[1][r0] * expf(redm[1][r0] - Ma);
        scl0 = expf(mx0 - Ma) / den0;
        float Mb = fmaxf(redm[0][r1], redm[1][r1]);
        float den1 = reds[0][r1] * expf(redm[0][r1] - Mb)
                   + reds[1][r1] * expf(redm[1][r1] - Mb);
        scl1 = expf(mx1 - Mb) / den1;
    }

    // ---- pack P into A-fragments
    uint32_t aP[2][4];
#pragma unroll
    for (int kj = 0; kj < 2; kj++) {
        int njl = kj * 2, njh = kj * 2 + 1;
        aP[kj][0] = pk2(e[njl][0] * scl0, e[njl][1] * scl0);
        aP[kj][1] = pk2(e[njl][2] * scl1, e[njl][3] * scl1);
        aP[kj][2] = pk2(e[njh][0] * scl0, e[njh][1] * scl0);
        aP[kj][3] = pk2(e[njh][2] * scl1, e[njh][3] * scl1);
    }

    // ---- O partial = P(band) V(band)
    float accO[4][4];
#pragma unroll
    for (int dj = 0; dj < 4; dj++)
#pragma unroll
        for (int l = 0; l < 4; l++) accO[dj][l] = 0.f;
#pragma unroll
    for (int kj = 0; kj < 2; kj++) {
        int kbase = n00 + (kj << 4) + (tq << 1);
#pragma unroll
        for (int dj = 0; dj < 4; dj++) {
            uint32_t b0 = *(const uint32_t*)&svT[(dj << 3) + g][kbase];
            uint32_t b1 = *(const uint32_t*)&svT[(dj << 3) + g][kbase + 8];
            mma16(accO[dj], aP[kj], b0, b1);
        }
    }
#pragma unroll
    for (int dj = 0; dj < 4; dj++)
#pragma unroll
        for (int hr = 0; hr < 2; hr++) {
            int rr = tn0 + g + (hr << 3);
            int dd = (dj << 3) + (tq << 1);
            *(float2*)&soP[wn][rr][dd] =
                make_float2(accO[dj][hr * 2], accO[dj][hr * 2 + 1]);
        }
    __syncthreads();

    // ---- combine bands + pack fp16 A-layout
    {
        int kb16L = tid >> 7;
        int grpL  = (tid >> 5) & 3;
        int ln2   = tid & 31;
        int lr    = (grpL << 4) + (ln2 >> 2);
        int c0    = (kb16L << 4) + ((ln2 & 3) << 1);
        uint4 o;
        o.x = pk2(soP[0][lr][c0]         + soP[1][lr][c0],
                  soP[0][lr][c0 + 1]     + soP[1][lr][c0 + 1]);
        o.y = pk2(soP[0][lr + 8][c0]     + soP[1][lr + 8][c0],
                  soP[0][lr + 8][c0 + 1] + soP[1][lr + 8][c0 + 1]);
        o.z = pk2(soP[0][lr][c0 + 8]     + soP[1][lr][c0 + 8],
                  soP[0][lr][c0 + 9]     + soP[1][lr][c0 + 9]);
        o.w = pk2(soP[0][lr + 8][c0 + 8] + soP[1][lr + 8][c0 + 8],
                  soP[0][lr + 8][c0 + 9] + soP[1][lr + 8][c0 + 9]);
        *(uint4*)(outA + tbase + (size_t)(2 * h + kb16L) * 2048
                  + (size_t)(grpBase + grpL) * 256 + ln2 * 8) = o;
    }
}

// ---------------------------------------------------------------------------
extern "C" void kernel_launch(void* const* d_in, const int* in_sizes, int n_in,
                              void* d_out, int out_size) {
    const float* x      = (const float*)d_in[0];
    const float* skip   = (const float*)d_in[1];
    const float* n1g    = (const float*)d_in[2];
    const float* n1b    = (const float*)d_in[3];
    const float* w_qkv  = (const float*)d_in[4];
    const float* b_qkv  = (const float*)d_in[5];
    const float* w_skip = (const float*)d_in[6];
    const float* b_skip = (const float*)d_in[7];
    const float* relb   = (const float*)d_in[8];
    const float* w_proj = (const float*)d_in[9];
    const float* b_proj = (const float*)d_in[10];
    const float* n2g    = (const float*)d_in[11];
    const float* n2b    = (const float*)d_in[12];
    const float* w_fc1  = (const float*)d_in[13];
    const float* b_fc1  = (const float*)d_in[14];
    const float* w_fc2  = (const float*)d_in[15];
    const float* b_fc2  = (const float*)d_in[16];
    float* outp = (float*)d_out;

    __half *axA, *asA, *hA, *wqB, *wsB, *wpB, *w1B, *w2B, *kvb, *qb;
    float *xres;
    cudaGetSymbolAddress((void**)&axA, g_axA);
    cudaGetSymbolAddress((void**)&asA, g_asA);
    cudaGetSymbolAddress((void**)&kvb, g_kv);
    cudaGetSymbolAddress((void**)&qb,  g_q);
    cudaGetSymbolAddress((void**)&xres, g_xres);
    cudaGetSymbolAddress((void**)&hA,  g_hA);
    cudaGetSymbolAddress((void**)&wqB, g_wqkvB);
    cudaGetSymbolAddress((void**)&wsB, g_wskipB);
    cudaGetSymbolAddress((void**)&wpB, g_wprojB);
    cudaGetSymbolAddress((void**)&w1B, g_wfc1B);
    cudaGetSymbolAddress((void**)&w2B, g_wfc2B);

    cudaFuncSetAttribute(gemm_h<0>, cudaFuncAttributeMaxDynamicSharedMemorySize, GEMM_SMEM);
    cudaFuncSetAttribute(gemm_h<1>, cudaFuncAttributeMaxDynamicSharedMemorySize, GEMM_SMEM);
    cudaFuncSetAttribute(gemm_h<2>, cudaFuncAttributeMaxDynamicSharedMemorySize, GEMM_SMEM);
    cudaFuncSetAttribute(gemm_h<3>, cudaFuncAttributeMaxDynamicSharedMemorySize, GEMM_SMEM);
    cudaFuncSetAttribute(gemm_h<4>, cudaFuncAttributeMaxDynamicSharedMemorySize, GEMM_SMEM);

    wconv_all<<<1536, 256>>>(w_qkv, w_skip, w_proj, w_fc1, w_fc2,
                             wqB, wsB, wpB, w1B, w2B);

    ln1_kernel<<<4096, 512>>>(x, skip, n1g, n1b, axA, asA);
    gemm_h<0><<<dim3(8, 512), 256, GEMM_SMEM>>>(axA, wqB, b_qkv, nullptr, nullptr, kvb, 1024, 512);
    gemm_h<1><<<dim3(4, 512), 256, GEMM_SMEM>>>(asA, wsB, b_skip, nullptr, nullptr, qb, 512, 512);
    attn_kernel<<<dim3(1024, 16), 256>>>(qb, kvb, relb, asA);
    gemm_h<2><<<dim3(4, 512), 256, GEMM_SMEM>>>(asA, wpB, b_proj, xres, x, nullptr, 512, 512);
    ln2_kernel<<<4096, 512>>>(xres, n2g, n2b, axA);
    gemm_h<3><<<dim3(16, 512), 256, GEMM_SMEM>>>(axA, w1B, b_fc1, nullptr, nullptr, hA, 2048, 512);
    gemm_h<4><<<dim3(4, 512), 256, GEMM_SMEM>>>(hA, w2B, b_fc2, outp, xres, nullptr, 512, 2048);
    (void)in_sizes; (void)n_in; (void)out_size;
}